// round 1
// baseline (speedup 1.0000x reference)
#include <cuda_runtime.h>
#include <cstdint>

// ---------------- problem constants (fixed by setup_inputs) ----------------
#define NPTS 200000
#define CDIM 128
#define BDIM 4
#define HFD  116
#define WFD  200
#define HIDD 64
// float(WF)/float(img_w) = 200/1600 = 0.125, float(HF)/float(img_h) = 116/928 = 0.125

// ---------------- global scratch (static: no allocations) ------------------
__device__ float g_imgT[(size_t)BDIM * HFD * WFD * CDIM];  // (B,H,W,C) ~47.5MB
__device__ float g_samp[(size_t)NPTS * CDIM];              // sampled feats ~102MB
__device__ float g_hid [(size_t)NPTS * CDIM];              // le hidden     ~102MB
__device__ float g_scal[(size_t)NPTS * 8];                 // per-point scalars

// ---------------- f32x2 helpers (packed dual-FMA on sm_103a) ---------------
typedef unsigned long long u64;

__device__ __forceinline__ u64 pk2(float lo, float hi) {
    u64 r; asm("mov.b64 %0,{%1,%2};" : "=l"(r) : "f"(lo), "f"(hi)); return r;
}
__device__ __forceinline__ float2 up2(u64 v) {
    float2 r; asm("mov.b64 {%0,%1},%2;" : "=f"(r.x), "=f"(r.y) : "l"(v)); return r;
}
__device__ __forceinline__ u64 f2fma(u64 a, u64 b, u64 c) {
    u64 d; asm("fma.rn.f32x2 %0,%1,%2,%3;" : "=l"(d) : "l"(a), "l"(b), "l"(c)); return d;
}
__device__ __forceinline__ float clip01(float v) { return fminf(fmaxf(v, 0.f), 1.f); }

// ============================================================================
// K1: transpose img_feats (B,C,H,W) -> g_imgT (B,H,W,C)
// ============================================================================
__global__ void k_transpose(const float* __restrict__ img) {
    __shared__ float s[32][33];
    int b  = blockIdx.z;
    int y  = blockIdx.y;
    int ct = blockIdx.x & 3;      // 4 channel tiles (C=128)
    int xt = blockIdx.x >> 2;     // 7 x tiles (W=200)
    int tx = threadIdx.x, ty = threadIdx.y;

    int ci = ct * 32 + ty;
    int xi = xt * 32 + tx;
    if (xi < WFD)
        s[ty][tx] = img[(((size_t)b * CDIM + ci) * HFD + y) * WFD + xi];
    __syncthreads();

    int xo = xt * 32 + ty;
    int co = ct * 32 + tx;
    if (xo < WFD)
        g_imgT[(((size_t)b * HFD + y) * WFD + xo) * CDIM + co] = s[tx][ty];
}

// ============================================================================
// K2: per-point geometry + projection + fused fg/rt MLPs + bilinear sampling
// ============================================================================
__global__ __launch_bounds__(256) void k_point(
    const float* __restrict__ x, const int* __restrict__ indices,
    const float* __restrict__ vox, const float* __restrict__ pcr,
    const float* __restrict__ trans,
    const float* __restrict__ fgw1, const float* __restrict__ fgb1,
    const float* __restrict__ fgw2, const float* __restrict__ fgb2,
    const float* __restrict__ rtw1, const float* __restrict__ rtb1,
    const float* __restrict__ rtw2, const float* __restrict__ rtb2)
{
    int p = blockIdx.x * 256 + threadIdx.x;
    if (p >= NPTS) return;

    // ---- geometry ----
    int4 idx = ((const int4*)indices)[p];        // (b, z, y, x)
    int b = idx.x;
    float cv0 = vox[0] * 8.f, cv1 = vox[1] * 8.f, cv2 = vox[2] * 8.f;
    float cx = (float)idx.w * cv0 + pcr[0] + cv0 * 0.5f;
    float cy = (float)idx.z * cv1 + pcr[1] + cv1 * 0.5f;
    float cz = (float)idx.y * cv2 + pcr[2] + cv2 * 0.5f;
    float rn = clip01(sqrtf(cx * cx + cy * cy) * (1.0f / 72.0f));

    const float* P = trans + b * 12;
    float X0 = P[0] * cx + P[1] * cy + P[2]  * cz + P[3];
    float X1 = P[4] * cx + P[5] * cy + P[6]  * cz + P[7];
    float X2 = P[8] * cx + P[9] * cy + P[10] * cz + P[11];
    float safe = fmaxf(X2, 1e-5f);
    float uf = (X0 / safe) * 0.125f;
    float vf = (X1 / safe) * 0.125f;
    float un = 2.f * (uf / 199.f) - 1.f;
    float vn = 2.f * (vf / 115.f) - 1.f;
    float validf = (X2 > 1e-5f && fabsf(un) <= 1.f && fabsf(vn) <= 1.f) ? 1.f : 0.f;

    // ---- fused fg/rt hidden GEMVs (single sweep over x row) ----
    u64 aF[32], aR[32];
#pragma unroll
    for (int j = 0; j < 32; j++) {
        aF[j] = pk2(__ldg(fgb1 + 2 * j), __ldg(fgb1 + 2 * j + 1));
        aR[j] = pk2(__ldg(rtb1 + 2 * j), __ldg(rtb1 + 2 * j + 1));
    }
    const float4* xr = (const float4*)(x + (size_t)p * CDIM);
#pragma unroll 1
    for (int k4 = 0; k4 < 32; k4++) {
        float4 xv = __ldg(xr + k4);
        float xs[4] = {xv.x, xv.y, xv.z, xv.w};
#pragma unroll
        for (int s = 0; s < 4; s++) {
            int k = 4 * k4 + s;
            u64 xx = pk2(xs[s], xs[s]);
            const ulonglong2* wf = (const ulonglong2*)(fgw1 + (size_t)k * HIDD);
            const ulonglong2* wr = (const ulonglong2*)(rtw1 + (size_t)k * HIDD);
#pragma unroll
            for (int j = 0; j < 16; j++) {
                ulonglong2 a = __ldg(wf + j);
                ulonglong2 c = __ldg(wr + j);
                aF[2 * j]     = f2fma(xx, a.x, aF[2 * j]);
                aF[2 * j + 1] = f2fma(xx, a.y, aF[2 * j + 1]);
                aR[2 * j]     = f2fma(xx, c.x, aR[2 * j]);
                aR[2 * j + 1] = f2fma(xx, c.y, aR[2 * j + 1]);
            }
        }
    }

    // ---- fg head: relu -> dot fg_w2 -> sigmoid ----
    float s1 = __ldg(fgb2);
#pragma unroll
    for (int j = 0; j < 32; j++) {
        float2 h = up2(aF[j]);
        s1 += fmaxf(h.x, 0.f) * __ldg(fgw2 + 2 * j) + fmaxf(h.y, 0.f) * __ldg(fgw2 + 2 * j + 1);
    }
    float pfg = 1.f / (1.f + __expf(-s1));

    // ---- rt tail rows: range_norm (128), p_fg (129), valid (130) ----
    {
        u64 t0 = pk2(rn, rn), t1 = pk2(pfg, pfg), t2 = pk2(validf, validf);
        const ulonglong2* r0p = (const ulonglong2*)(rtw1 + 128 * HIDD);
        const ulonglong2* r1p = (const ulonglong2*)(rtw1 + 129 * HIDD);
        const ulonglong2* r2p = (const ulonglong2*)(rtw1 + 130 * HIDD);
#pragma unroll
        for (int j = 0; j < 16; j++) {
            ulonglong2 a = __ldg(r0p + j), c = __ldg(r1p + j), d = __ldg(r2p + j);
            aR[2 * j]     = f2fma(t0, a.x, aR[2 * j]);
            aR[2 * j + 1] = f2fma(t0, a.y, aR[2 * j + 1]);
            aR[2 * j]     = f2fma(t1, c.x, aR[2 * j]);
            aR[2 * j + 1] = f2fma(t1, c.y, aR[2 * j + 1]);
            aR[2 * j]     = f2fma(t2, d.x, aR[2 * j]);
            aR[2 * j + 1] = f2fma(t2, d.y, aR[2 * j + 1]);
        }
    }

    // ---- rt head: relu -> (64x3) -> softmax ----
    float r0 = __ldg(rtb2 + 0), r1 = __ldg(rtb2 + 1), r2 = __ldg(rtb2 + 2);
#pragma unroll
    for (int j = 0; j < 32; j++) {
        float2 h = up2(aR[j]);
        float h0 = fmaxf(h.x, 0.f), h1 = fmaxf(h.y, 0.f);
        r0 += h0 * __ldg(rtw2 + (2 * j) * 3 + 0) + h1 * __ldg(rtw2 + (2 * j + 1) * 3 + 0);
        r1 += h0 * __ldg(rtw2 + (2 * j) * 3 + 1) + h1 * __ldg(rtw2 + (2 * j + 1) * 3 + 1);
        r2 += h0 * __ldg(rtw2 + (2 * j) * 3 + 2) + h1 * __ldg(rtw2 + (2 * j + 1) * 3 + 2);
    }
    float m  = fmaxf(r0, fmaxf(r1, r2));
    float e0 = __expf(r0 - m), e1 = __expf(r1 - m), e2 = __expf(r2 - m);
    float inv = 1.f / (e0 + e1 + e2);
    float w0 = e0 * inv, w1 = e1 * inv, w2 = e2 * inv;

    float4* sc = (float4*)(g_scal + (size_t)p * 8);
    sc[0] = make_float4(w0, w1, w2, pfg);
    sc[1] = make_float4(rn, validf, 0.f, 0.f);

    // ---- bilinear sample (from transposed BHWC image) ----
    float px = (un + 1.f) * 0.5f * 199.f;
    float py = (vn + 1.f) * 0.5f * 115.f;
    float x0f = floorf(px), y0f = floorf(py);
    float fx = px - x0f, fy = py - y0f;
    int xi0 = (int)x0f, yi0 = (int)y0f;
    int xi1 = xi0 + 1,  yi1 = yi0 + 1;
    float bx0 = (xi0 >= 0 && xi0 < WFD) ? 1.f : 0.f;
    float bx1 = (xi1 >= 0 && xi1 < WFD) ? 1.f : 0.f;
    float by0 = (yi0 >= 0 && yi0 < HFD) ? 1.f : 0.f;
    float by1 = (yi1 >= 0 && yi1 < HFD) ? 1.f : 0.f;
    float w00 = (1.f - fx) * (1.f - fy) * bx0 * by0;
    float w01 = fx * (1.f - fy) * bx1 * by0;
    float w10 = (1.f - fx) * fy * bx0 * by1;
    float w11 = fx * fy * bx1 * by1;
    int xc0 = min(max(xi0, 0), WFD - 1), xc1 = min(max(xi1, 0), WFD - 1);
    int yc0 = min(max(yi0, 0), HFD - 1), yc1 = min(max(yi1, 0), HFD - 1);

    const float4* p00 = (const float4*)(g_imgT + (((size_t)b * HFD + yc0) * WFD + xc0) * CDIM);
    const float4* p01 = (const float4*)(g_imgT + (((size_t)b * HFD + yc0) * WFD + xc1) * CDIM);
    const float4* p10 = (const float4*)(g_imgT + (((size_t)b * HFD + yc1) * WFD + xc0) * CDIM);
    const float4* p11 = (const float4*)(g_imgT + (((size_t)b * HFD + yc1) * WFD + xc1) * CDIM);
    float4* so = (float4*)(g_samp + (size_t)p * CDIM);
#pragma unroll 4
    for (int j = 0; j < 32; j++) {
        float4 a = __ldg(p00 + j), bq = __ldg(p01 + j), cq = __ldg(p10 + j), dq = __ldg(p11 + j);
        float4 r;
        r.x = w00 * a.x + w01 * bq.x + w10 * cq.x + w11 * dq.x;
        r.y = w00 * a.y + w01 * bq.y + w10 * cq.y + w11 * dq.y;
        r.z = w00 * a.z + w01 * bq.z + w10 * cq.z + w11 * dq.z;
        r.w = w00 * a.w + w01 * bq.w + w10 * cq.w + w11 * dq.w;
        so[j] = r;
    }
}

// ============================================================================
// K3: hid = relu([x | samp] @ le_w1 + le_b1), le_w1 (256x128) in shared
// ============================================================================
__global__ __launch_bounds__(256, 1) void k_layer1(
    const float* __restrict__ x, const float* __restrict__ lew1,
    const float* __restrict__ leb1)
{
    extern __shared__ float ws[];   // 256*128 floats = 128KB
    int tid = threadIdx.x;
    {
        const float4* src = (const float4*)lew1;
        float4* dst = (float4*)ws;
        for (int i = tid; i < (256 * 128) / 4; i += 256) dst[i] = __ldg(src + i);
    }
    __syncthreads();

    int p = blockIdx.x * 256 + tid;
    if (p >= NPTS) return;

    u64 acc[64];
#pragma unroll
    for (int j = 0; j < 64; j++) acc[j] = pk2(__ldg(leb1 + 2 * j), __ldg(leb1 + 2 * j + 1));

    const float4* h0 = (const float4*)(x      + (size_t)p * CDIM);
    const float4* h1 = (const float4*)(g_samp + (size_t)p * CDIM);

#pragma unroll 1
    for (int k4 = 0; k4 < 32; k4++) {
        float4 hv = __ldg(h0 + k4);
        float hs[4] = {hv.x, hv.y, hv.z, hv.w};
#pragma unroll
        for (int s = 0; s < 4; s++) {
            u64 xx = pk2(hs[s], hs[s]);
            const ulonglong2* wrow = (const ulonglong2*)(ws + (size_t)(4 * k4 + s) * CDIM);
#pragma unroll
            for (int j = 0; j < 32; j++) {
                ulonglong2 w = wrow[j];
                acc[2 * j]     = f2fma(xx, w.x, acc[2 * j]);
                acc[2 * j + 1] = f2fma(xx, w.y, acc[2 * j + 1]);
            }
        }
    }
#pragma unroll 1
    for (int k4 = 0; k4 < 32; k4++) {
        float4 hv = __ldg(h1 + k4);
        float hs[4] = {hv.x, hv.y, hv.z, hv.w};
#pragma unroll
        for (int s = 0; s < 4; s++) {
            u64 xx = pk2(hs[s], hs[s]);
            const ulonglong2* wrow = (const ulonglong2*)(ws + (size_t)(128 + 4 * k4 + s) * CDIM);
#pragma unroll
            for (int j = 0; j < 32; j++) {
                ulonglong2 w = wrow[j];
                acc[2 * j]     = f2fma(xx, w.x, acc[2 * j]);
                acc[2 * j + 1] = f2fma(xx, w.y, acc[2 * j + 1]);
            }
        }
    }

    float4* o = (float4*)(g_hid + (size_t)p * CDIM);
#pragma unroll
    for (int j = 0; j < 32; j++) {
        float2 a = up2(acc[2 * j]), c = up2(acc[2 * j + 1]);
        o[j] = make_float4(fmaxf(a.x, 0.f), fmaxf(a.y, 0.f), fmaxf(c.x, 0.f), fmaxf(c.y, 0.f));
    }
}

// ============================================================================
// K4: delta = rw1*valid*(hid @ le_w2 + le_b2); layernorm; quality. w2 in shared
// ============================================================================
__global__ __launch_bounds__(256, 1) void k_layer2(
    const float* __restrict__ x, const float* __restrict__ lew2,
    const float* __restrict__ leb2, const float* __restrict__ lng,
    const float* __restrict__ lnb, float* __restrict__ out)
{
    extern __shared__ float ws[];   // 128*128 floats = 64KB
    int tid = threadIdx.x;
    {
        const float4* src = (const float4*)lew2;
        float4* dst = (float4*)ws;
        for (int i = tid; i < (128 * 128) / 4; i += 256) dst[i] = __ldg(src + i);
    }
    __syncthreads();

    int p = blockIdx.x * 256 + tid;
    if (p >= NPTS) return;

    u64 acc[64];
#pragma unroll
    for (int j = 0; j < 64; j++) acc[j] = pk2(__ldg(leb2 + 2 * j), __ldg(leb2 + 2 * j + 1));

    const float4* hr = (const float4*)(g_hid + (size_t)p * CDIM);
#pragma unroll 1
    for (int k4 = 0; k4 < 32; k4++) {
        float4 hv = __ldg(hr + k4);
        float hs[4] = {hv.x, hv.y, hv.z, hv.w};
#pragma unroll
        for (int s = 0; s < 4; s++) {
            u64 xx = pk2(hs[s], hs[s]);
            const ulonglong2* wrow = (const ulonglong2*)(ws + (size_t)(4 * k4 + s) * CDIM);
#pragma unroll
            for (int j = 0; j < 32; j++) {
                ulonglong2 w = wrow[j];
                acc[2 * j]     = f2fma(xx, w.x, acc[2 * j]);
                acc[2 * j + 1] = f2fma(xx, w.y, acc[2 * j + 1]);
            }
        }
    }

    // ---- epilogue ----
    float4 s0 = ((const float4*)(g_scal + (size_t)p * 8))[0];
    float4 s1v = ((const float4*)(g_scal + (size_t)p * 8))[1];
    float rw0 = s0.x, rw1 = s0.y, rw2 = s0.z, pfg = s0.w;
    float rn = s1v.x, validf = s1v.y;
    float scale = rw1 * validf;

    const float4* xr = (const float4*)(x + (size_t)p * CDIM);
    float sum = 0.f, sumsq = 0.f, nd = 0.f, nx = 0.f;
#pragma unroll
    for (int j = 0; j < 32; j++) {
        float4 xv = __ldg(xr + j);
        float2 a = up2(acc[2 * j]), c = up2(acc[2 * j + 1]);
        float d0 = scale * a.x, d1 = scale * a.y, d2 = scale * c.x, d3 = scale * c.y;
        acc[2 * j] = pk2(d0, d1); acc[2 * j + 1] = pk2(d2, d3);   // keep delta
        float h0 = xv.x + d0, h1 = xv.y + d1, h2 = xv.z + d2, h3 = xv.w + d3;
        sum   += h0 + h1 + h2 + h3;
        sumsq += h0 * h0 + h1 * h1 + h2 * h2 + h3 * h3;
        nd    += d0 * d0 + d1 * d1 + d2 * d2 + d3 * d3;
        nx    += xv.x * xv.x + xv.y * xv.y + xv.z * xv.z + xv.w * xv.w;
    }
    float mu  = sum * (1.f / 128.f);
    float var = fmaxf(sumsq * (1.f / 128.f) - mu * mu, 0.f);
    float rstd = rsqrtf(var + 1e-5f);
    float gq   = sqrtf(nd) / (sqrtf(nx) + 1e-6f);
    float gain = clip01(1.f - __expf(-gq));

    float4* fo = (float4*)(out + (size_t)p * CDIM);
#pragma unroll
    for (int j = 0; j < 32; j++) {
        float4 xv = __ldg(xr + j);
        float2 a = up2(acc[2 * j]), c = up2(acc[2 * j + 1]);
        float4 g4 = __ldg(((const float4*)lng) + j);
        float4 b4 = __ldg(((const float4*)lnb) + j);
        float4 r;
        r.x = (xv.x + a.x - mu) * rstd * g4.x + b4.x;
        r.y = (xv.y + a.y - mu) * rstd * g4.y + b4.y;
        r.z = (xv.z + c.x - mu) * rstd * g4.z + b4.z;
        r.w = (xv.w + c.y - mu) * rstd * g4.w + b4.w;
        fo[j] = r;
    }

    float* q = out + (size_t)NPTS * CDIM + (size_t)p * 11;
    q[0] = clip01(rw0);  q[1] = clip01(rw1);  q[2] = clip01(rw2);
    q[3] = clip01(pfg);  q[4] = clip01(rn);   q[5] = clip01(validf);
    q[6] = 0.f;          q[7] = gain;         q[8] = 0.f;
    q[9] = 0.f;          q[10] = 0.f;
}

// ============================================================================
// launch
// ============================================================================
extern "C" void kernel_launch(void* const* d_in, const int* in_sizes, int n_in,
                              void* d_out, int out_size)
{
    const float* x       = (const float*)d_in[0];
    const int*   indices = (const int*)  d_in[1];
    const float* vox     = (const float*)d_in[2];
    const float* pcr     = (const float*)d_in[3];
    const float* trans   = (const float*)d_in[4];
    const float* img     = (const float*)d_in[5];

    // img_h / img_w scalars may or may not be materialized as inputs.
    int base = 6;
    if (n_in >= 8 && in_sizes[6] == 1 && in_sizes[7] == 1) base = 8;

    const float* fgw1 = (const float*)d_in[base + 0];
    const float* fgb1 = (const float*)d_in[base + 1];
    const float* fgw2 = (const float*)d_in[base + 2];
    const float* fgb2 = (const float*)d_in[base + 3];
    const float* rtw1 = (const float*)d_in[base + 4];
    const float* rtb1 = (const float*)d_in[base + 5];
    const float* rtw2 = (const float*)d_in[base + 6];
    const float* rtb2 = (const float*)d_in[base + 7];
    const float* lew1 = (const float*)d_in[base + 8];
    const float* leb1 = (const float*)d_in[base + 9];
    const float* lew2 = (const float*)d_in[base + 10];
    const float* leb2 = (const float*)d_in[base + 11];
    const float* lng  = (const float*)d_in[base + 12];
    const float* lnb  = (const float*)d_in[base + 13];
    float* out = (float*)d_out;

    cudaFuncSetAttribute(k_layer1, cudaFuncAttributeMaxDynamicSharedMemorySize, 131072);
    cudaFuncSetAttribute(k_layer2, cudaFuncAttributeMaxDynamicSharedMemorySize, 65536);

    dim3 tb(32, 32);
    k_transpose<<<dim3(28, HFD, BDIM), tb>>>(img);

    int nblk = (NPTS + 255) / 256;
    k_point<<<nblk, 256>>>(x, indices, vox, pcr, trans,
                           fgw1, fgb1, fgw2, fgb2, rtw1, rtb1, rtw2, rtb2);
    k_layer1<<<nblk, 256, 131072>>>(x, lew1, leb1);
    k_layer2<<<nblk, 256, 65536>>>(x, lew2, leb2, lng, lnb, out);
}

// round 4
// speedup vs baseline: 2.0625x; 2.0625x over previous
#include <cuda_runtime.h>
#include <cstdint>

// ---------------- problem constants ----------------
#define NPTS 200000
#define NPAD 200064              // 128 * 1563 (padded point count)
#define CDIM 128
#define HFD  116
#define WFD  200
#define BDIM 4

typedef unsigned long long u64;

// ---------------- global scratch (zero-initialized device globals) ---------
__device__ float g_imgT [(size_t)BDIM * HFD * WFD * CDIM];  // (B,H,W,C)
__device__ float g_xT   [(size_t)CDIM * NPAD];              // x transposed [c][pt]
__device__ float g_preT [(size_t)CDIM * NPAD];              // fg|rt preact [c][pt]
__device__ float g_sampT[(size_t)CDIM * NPAD];              // sampled [c][pt]
__device__ float g_hidT [(size_t)CDIM * NPAD];              // le hidden [c][pt]
__device__ float g_sw1v [NPAD];                             // rw1 * valid

// ---------------- f32x2 helpers ----------------
__device__ __forceinline__ u64 pk2(float lo, float hi) {
    u64 r; asm("mov.b64 %0,{%1,%2};" : "=l"(r) : "f"(lo), "f"(hi)); return r;
}
__device__ __forceinline__ float2 up2(u64 v) {
    float2 r; asm("mov.b64 {%0,%1},%2;" : "=f"(r.x), "=f"(r.y) : "l"(v)); return r;
}
__device__ __forceinline__ u64 f2fma(u64 a, u64 b, u64 c) {
    u64 d; asm("fma.rn.f32x2 %0,%1,%2,%3;" : "=l"(d) : "l"(a), "l"(b), "l"(c)); return d;
}
__device__ __forceinline__ u64 f2mul(u64 a, u64 b) {
    u64 d; asm("mul.rn.f32x2 %0,%1,%2;" : "=l"(d) : "l"(a), "l"(b)); return d;
}
__device__ __forceinline__ u64 f2add(u64 a, u64 b) {
    u64 d; asm("add.rn.f32x2 %0,%1,%2;" : "=l"(d) : "l"(a), "l"(b)); return d;
}
__device__ __forceinline__ float clip01(float v) { return fminf(fmaxf(v, 0.f), 1.f); }

// ============================================================================
// transpose kernels
// ============================================================================
__global__ void k_tr_img(const float* __restrict__ img) {
    __shared__ float s[32][33];
    int b  = blockIdx.z;
    int y  = blockIdx.y;
    int ct = blockIdx.x & 3;
    int xt = blockIdx.x >> 2;
    int tx = threadIdx.x, ty = threadIdx.y;
    int ci = ct * 32 + ty;
    int xi = xt * 32 + tx;
    if (xi < WFD)
        s[ty][tx] = img[(((size_t)b * CDIM + ci) * HFD + y) * WFD + xi];
    __syncthreads();
    int xo = xt * 32 + ty;
    int co = ct * 32 + tx;
    if (xo < WFD)
        g_imgT[(((size_t)b * HFD + y) * WFD + xo) * CDIM + co] = s[tx][ty];
}

__global__ void k_tr_x(const float* __restrict__ x) {
    __shared__ float s[32][33];
    int pt0 = blockIdx.x * 32, c0 = blockIdx.y * 32;
    int tx = threadIdx.x, ty = threadIdx.y;
    int pt = pt0 + ty;
    s[ty][tx] = (pt < NPTS) ? x[(size_t)pt * CDIM + c0 + tx] : 0.f;
    __syncthreads();
    g_xT[(size_t)(c0 + ty) * NPAD + pt0 + tx] = s[tx][ty];
}

// ============================================================================
// tiled GEMM core: block = 128 pts x 128 cols, K-chunk = 128
// 256 threads: warpCol = warp&3 (32 cols), warpRow = warp>>2 (64 pts)
// lane: cg = lane&3 (col base cg*2, stride 8), pg = lane>>2 (pt base pg, stride 8)
// per thread: 8 pts x 8 cols (4 col-pairs packed in f32x2)
// ============================================================================
__device__ __forceinline__ void load_x_tile(float* xs, const float* __restrict__ src,
                                            int ptBase, int tid) {
#pragma unroll
    for (int it = 0; it < 16; it++) {
        int idx = tid + it * 256;
        int k = idx >> 5, q = idx & 31;
        float4 v = __ldg((const float4*)(src + (size_t)k * NPAD + ptBase) + q);
        *((float4*)(xs + k * 128) + q) = v;
    }
}
__device__ __forceinline__ void load_w_tile(float* ws, const float* __restrict__ W, int tid) {
#pragma unroll
    for (int it = 0; it < 16; it++) {
        int idx = tid + it * 256;
        int k = idx >> 5, q = idx & 31;
        *((float4*)(ws + k * 128) + q) = __ldg((const float4*)(W + (size_t)k * 128) + q);
    }
}

__device__ __forceinline__ void gemm_tile(const float* __restrict__ xs,
                                          const float* __restrict__ ws,
                                          int ptOff, int colOff, u64 acc[8][4]) {
#pragma unroll 4
    for (int k = 0; k < 128; k++) {
        const float* xr = xs + k * 128 + ptOff;
        const float* wr = ws + k * 128 + colOff;
        u64 w0 = *(const u64*)(wr);
        u64 w1 = *(const u64*)(wr + 8);
        u64 w2 = *(const u64*)(wr + 16);
        u64 w3 = *(const u64*)(wr + 24);
#pragma unroll
        for (int i = 0; i < 8; i++) {
            float xv = xr[8 * i];
            u64 xx = pk2(xv, xv);
            acc[i][0] = f2fma(xx, w0, acc[i][0]);
            acc[i][1] = f2fma(xx, w1, acc[i][1]);
            acc[i][2] = f2fma(xx, w2, acc[i][2]);
            acc[i][3] = f2fma(xx, w3, acc[i][3]);
        }
    }
}

// ============================================================================
// gemmA: preT = x @ [fg_w1 | rt_w1[:128]]   (no bias, raw preact)
// ============================================================================
__global__ __launch_bounds__(256, 1) void k_gemmA(const float* __restrict__ fgw1,
                                                  const float* __restrict__ rtw1) {
    extern __shared__ float sm[];
    float* ws = sm;
    float* xs = sm + 128 * 128;
    int tid = threadIdx.x;
    int ptBase = blockIdx.x * 128;

#pragma unroll
    for (int it = 0; it < 16; it++) {
        int idx = tid + it * 256;
        int k = idx >> 5, q = idx & 31;
        float4 v;
        if (q < 16) v = __ldg((const float4*)(fgw1 + (size_t)k * 64) + q);
        else        v = __ldg((const float4*)(rtw1 + (size_t)k * 64) + (q - 16));
        *((float4*)(ws + k * 128) + q) = v;
    }
    load_x_tile(xs, g_xT, ptBase, tid);
    __syncthreads();

    int warp = tid >> 5, lane = tid & 31;
    int wc = warp & 3, wr_ = warp >> 2, cg = lane & 3, pg = lane >> 2;
    int colOff = wc * 32 + cg * 2;
    int ptOff  = wr_ * 64 + pg;

    u64 acc[8][4];
#pragma unroll
    for (int i = 0; i < 8; i++)
#pragma unroll
        for (int j = 0; j < 4; j++) acc[i][j] = 0ull;

    gemm_tile(xs, ws, ptOff, colOff, acc);

#pragma unroll
    for (int i = 0; i < 8; i++) {
        int pt = ptBase + ptOff + 8 * i;
#pragma unroll
        for (int j = 0; j < 4; j++) {
            float2 v = up2(acc[i][j]);
            int c = colOff + 8 * j;
            g_preT[(size_t)c * NPAD + pt]       = v.x;
            g_preT[(size_t)(c + 1) * NPAD + pt] = v.y;
        }
    }
}

// ============================================================================
// le layer 1: hidT = relu([x | samp] @ le_w1 + le_b1)  (2 K-chunks)
// ============================================================================
__global__ __launch_bounds__(256, 1) void k_le1(const float* __restrict__ lew1,
                                                const float* __restrict__ leb1) {
    extern __shared__ float sm[];
    float* ws = sm;
    float* xs = sm + 128 * 128;
    int tid = threadIdx.x;
    int ptBase = blockIdx.x * 128;

    int warp = tid >> 5, lane = tid & 31;
    int wc = warp & 3, wr_ = warp >> 2, cg = lane & 3, pg = lane >> 2;
    int colOff = wc * 32 + cg * 2;
    int ptOff  = wr_ * 64 + pg;

    u64 acc[8][4];
    {
        u64 b0 = __ldg((const u64*)(leb1 + colOff));
        u64 b1 = __ldg((const u64*)(leb1 + colOff + 8));
        u64 b2 = __ldg((const u64*)(leb1 + colOff + 16));
        u64 b3 = __ldg((const u64*)(leb1 + colOff + 24));
#pragma unroll
        for (int i = 0; i < 8; i++) { acc[i][0]=b0; acc[i][1]=b1; acc[i][2]=b2; acc[i][3]=b3; }
    }

    // chunk 0: x rows 0..127
    load_w_tile(ws, lew1, tid);
    load_x_tile(xs, g_xT, ptBase, tid);
    __syncthreads();
    gemm_tile(xs, ws, ptOff, colOff, acc);
    __syncthreads();

    // chunk 1: samp rows 128..255
    load_w_tile(ws, lew1 + 128 * 128, tid);
    load_x_tile(xs, g_sampT, ptBase, tid);
    __syncthreads();
    gemm_tile(xs, ws, ptOff, colOff, acc);

#pragma unroll
    for (int i = 0; i < 8; i++) {
        int pt = ptBase + ptOff + 8 * i;
#pragma unroll
        for (int j = 0; j < 4; j++) {
            float2 v = up2(acc[i][j]);
            int c = colOff + 8 * j;
            g_hidT[(size_t)c * NPAD + pt]       = fmaxf(v.x, 0.f);
            g_hidT[(size_t)(c + 1) * NPAD + pt] = fmaxf(v.y, 0.f);
        }
    }
}

// ============================================================================
// le layer 2 + fused epilogue (delta scale, stats, layernorm, quality gain)
// ============================================================================
__global__ __launch_bounds__(256, 1) void k_le2(const float* __restrict__ lew2,
                                                const float* __restrict__ leb2,
                                                const float* __restrict__ lng,
                                                const float* __restrict__ lnb,
                                                float* __restrict__ out) {
    extern __shared__ float sm[];
    float* ws = sm;
    float* xs = sm + 128 * 128;
    __shared__ float sred[4][128][4];
    __shared__ float smu[128], srstd[128];

    int tid = threadIdx.x;
    int ptBase = blockIdx.x * 128;

    int warp = tid >> 5, lane = tid & 31;
    int wc = warp & 3, wr_ = warp >> 2, cg = lane & 3, pg = lane >> 2;
    int colOff = wc * 32 + cg * 2;
    int ptOff  = wr_ * 64 + pg;

    u64 acc[8][4];
    {
        u64 b0 = __ldg((const u64*)(leb2 + colOff));
        u64 b1 = __ldg((const u64*)(leb2 + colOff + 8));
        u64 b2 = __ldg((const u64*)(leb2 + colOff + 16));
        u64 b3 = __ldg((const u64*)(leb2 + colOff + 24));
#pragma unroll
        for (int i = 0; i < 8; i++) { acc[i][0]=b0; acc[i][1]=b1; acc[i][2]=b2; acc[i][3]=b3; }
    }

    load_w_tile(ws, lew2, tid);
    load_x_tile(xs, g_hidT, ptBase, tid);
    __syncthreads();
    gemm_tile(xs, ws, ptOff, colOff, acc);

    // ---- scale by rw1*valid, form h = x + delta, per-point partial stats ----
    float st[8][4];
#pragma unroll
    for (int i = 0; i < 8; i++) {
        int pl = ptOff + 8 * i;
        int pt = ptBase + pl;
        float s = g_sw1v[pt];
        u64 sp = pk2(s, s);
        float s0 = 0.f, s1 = 0.f, s2 = 0.f, s3 = 0.f;
#pragma unroll
        for (int j = 0; j < 4; j++) {
            int c = colOff + 8 * j;
            u64 d = f2mul(acc[i][j], sp);
            float x0 = __ldg(g_xT + (size_t)c * NPAD + pt);
            float x1 = __ldg(g_xT + (size_t)(c + 1) * NPAD + pt);
            float2 dv = up2(d);
            float h0 = x0 + dv.x, h1 = x1 + dv.y;
            s0 += h0 + h1;
            s1 += h0 * h0 + h1 * h1;
            s2 += dv.x * dv.x + dv.y * dv.y;
            s3 += x0 * x0 + x1 * x1;
            acc[i][j] = pk2(h0, h1);
        }
        st[i][0] = s0; st[i][1] = s1; st[i][2] = s2; st[i][3] = s3;
    }
    // reduce across the 4 colGroups (lane bits 0-1)
#pragma unroll
    for (int i = 0; i < 8; i++)
#pragma unroll
        for (int k = 0; k < 4; k++) {
            st[i][k] += __shfl_xor_sync(0xFFFFFFFF, st[i][k], 1);
            st[i][k] += __shfl_xor_sync(0xFFFFFFFF, st[i][k], 2);
        }
    if (cg == 0) {
#pragma unroll
        for (int i = 0; i < 8; i++) {
            int pl = ptOff + 8 * i;
            sred[wc][pl][0] = st[i][0];
            sred[wc][pl][1] = st[i][1];
            sred[wc][pl][2] = st[i][2];
            sred[wc][pl][3] = st[i][3];
        }
    }
    __syncthreads();

    if (tid < 128) {
        float s0 = 0.f, s1 = 0.f, s2 = 0.f, s3 = 0.f;
#pragma unroll
        for (int w = 0; w < 4; w++) {
            s0 += sred[w][tid][0]; s1 += sred[w][tid][1];
            s2 += sred[w][tid][2]; s3 += sred[w][tid][3];
        }
        float mu  = s0 * (1.f / 128.f);
        float var = fmaxf(s1 * (1.f / 128.f) - mu * mu, 0.f);
        float rstd = rsqrtf(var + 1e-5f);
        smu[tid] = mu; srstd[tid] = rstd;
        int pt = ptBase + tid;
        if (pt < NPTS) {
            float gq = sqrtf(s2) / (sqrtf(s3) + 1e-6f);
            out[(size_t)NPTS * CDIM + (size_t)pt * 11 + 7] = clip01(1.f - __expf(-gq));
        }
    }
    __syncthreads();

    // ---- normalize and stage into shared (reuse dynamic smem) ----
    // stride 132 floats = 528 bytes: 16B-aligned for every row (132*4 % 16 == 0),
    // u64 staging writes stay 8B-aligned (c even).
    float* sout = sm;   // 128 x 132 floats = 67584B <= 128KB dyn
#pragma unroll
    for (int i = 0; i < 8; i++) {
        int pl = ptOff + 8 * i;
        float mu = smu[pl], rs = srstd[pl];
        u64 mun = pk2(-mu, -mu);
        u64 rsp = pk2(rs, rs);
#pragma unroll
        for (int j = 0; j < 4; j++) {
            int c = colOff + 8 * j;
            u64 g2 = __ldg((const u64*)(lng + c));
            u64 b2 = __ldg((const u64*)(lnb + c));
            u64 t = f2mul(f2add(acc[i][j], mun), rsp);
            u64 o = f2fma(t, g2, b2);
            *(u64*)(sout + pl * 132 + c) = o;
        }
    }
    __syncthreads();

    // ---- coalesced write-out: warp w handles 16 points ----
    {
        int l = lane;
        for (int r = 0; r < 16; r++) {
            int pl = warp * 16 + r;
            int pt = ptBase + pl;
            if (pt < NPTS) {
                float4 v = *(const float4*)(sout + pl * 132 + l * 4);
                ((float4*)(out + (size_t)pt * CDIM))[l] = v;
            }
        }
    }
}

// ============================================================================
// per-point kernel: geometry, fg/rt heads, quality, bilinear sample
// ============================================================================
__global__ __launch_bounds__(256) void k_point(
    const int* __restrict__ indices, const float* __restrict__ vox,
    const float* __restrict__ pcr, const float* __restrict__ trans,
    const float* __restrict__ fgb1, const float* __restrict__ fgw2,
    const float* __restrict__ fgb2,
    const float* __restrict__ rtw1, const float* __restrict__ rtb1,
    const float* __restrict__ rtw2, const float* __restrict__ rtb2,
    float* __restrict__ out)
{
    int p = blockIdx.x * 256 + threadIdx.x;
    if (p >= NPTS) return;

    // ---- geometry ----
    int4 idx = ((const int4*)indices)[p];
    int b = idx.x;
    float cv0 = vox[0] * 8.f, cv1 = vox[1] * 8.f, cv2 = vox[2] * 8.f;
    float cx = (float)idx.w * cv0 + pcr[0] + cv0 * 0.5f;
    float cy = (float)idx.z * cv1 + pcr[1] + cv1 * 0.5f;
    float cz = (float)idx.y * cv2 + pcr[2] + cv2 * 0.5f;
    float rn = clip01(sqrtf(cx * cx + cy * cy) * (1.0f / 72.0f));

    const float* P = trans + b * 12;
    float X0 = P[0] * cx + P[1] * cy + P[2]  * cz + P[3];
    float X1 = P[4] * cx + P[5] * cy + P[6]  * cz + P[7];
    float X2 = P[8] * cx + P[9] * cy + P[10] * cz + P[11];
    float safe = fmaxf(X2, 1e-5f);
    float un = 2.f * ((X0 / safe) * 0.125f / 199.f) - 1.f;
    float vn = 2.f * ((X1 / safe) * 0.125f / 115.f) - 1.f;
    float validf = (X2 > 1e-5f && fabsf(un) <= 1.f && fabsf(vn) <= 1.f) ? 1.f : 0.f;

    // ---- fg head: sigmoid(relu(pre+b1) . w2 + b2) ----
    float s1 = __ldg(fgb2);
#pragma unroll 4
    for (int c = 0; c < 64; c++) {
        float pre = g_preT[(size_t)c * NPAD + p] + __ldg(fgb1 + c);
        s1 += fmaxf(pre, 0.f) * __ldg(fgw2 + c);
    }
    float pfg = 1.f / (1.f + __expf(-s1));

    // ---- rt head ----
    float r0 = __ldg(rtb2 + 0), r1 = __ldg(rtb2 + 1), r2 = __ldg(rtb2 + 2);
#pragma unroll 4
    for (int j = 0; j < 64; j++) {
        float pre = g_preT[(size_t)(64 + j) * NPAD + p] + __ldg(rtb1 + j)
                  + rn     * __ldg(rtw1 + 128 * 64 + j)
                  + pfg    * __ldg(rtw1 + 129 * 64 + j)
                  + validf * __ldg(rtw1 + 130 * 64 + j);
        float h = fmaxf(pre, 0.f);
        r0 += h * __ldg(rtw2 + j * 3 + 0);
        r1 += h * __ldg(rtw2 + j * 3 + 1);
        r2 += h * __ldg(rtw2 + j * 3 + 2);
    }
    float m  = fmaxf(r0, fmaxf(r1, r2));
    float e0 = __expf(r0 - m), e1 = __expf(r1 - m), e2 = __expf(r2 - m);
    float inv = 1.f / (e0 + e1 + e2);
    float w0 = e0 * inv, w1 = e1 * inv, w2 = e2 * inv;

    g_sw1v[p] = w1 * validf;

    float* q = out + (size_t)NPTS * CDIM + (size_t)p * 11;
    q[0] = clip01(w0);  q[1] = clip01(w1);  q[2] = clip01(w2);
    q[3] = clip01(pfg); q[4] = rn;          q[5] = validf;
    q[6] = 0.f;         q[8] = 0.f;         q[9] = 0.f;  q[10] = 0.f;
    // q[7] (fusion gain) written by k_le2

    // ---- bilinear sample -> sampT [c][pt] ----
    float px = (un + 1.f) * 0.5f * 199.f;
    float py = (vn + 1.f) * 0.5f * 115.f;
    float x0f = floorf(px), y0f = floorf(py);
    float fx = px - x0f, fy = py - y0f;
    int xi0 = (int)x0f, yi0 = (int)y0f;
    int xi1 = xi0 + 1,  yi1 = yi0 + 1;
    float bx0 = (xi0 >= 0 && xi0 < WFD) ? 1.f : 0.f;
    float bx1 = (xi1 >= 0 && xi1 < WFD) ? 1.f : 0.f;
    float by0 = (yi0 >= 0 && yi0 < HFD) ? 1.f : 0.f;
    float by1 = (yi1 >= 0 && yi1 < HFD) ? 1.f : 0.f;
    float w00 = (1.f - fx) * (1.f - fy) * bx0 * by0;
    float w01 = fx * (1.f - fy) * bx1 * by0;
    float w10 = (1.f - fx) * fy * bx0 * by1;
    float w11 = fx * fy * bx1 * by1;
    int xc0 = min(max(xi0, 0), WFD - 1), xc1 = min(max(xi1, 0), WFD - 1);
    int yc0 = min(max(yi0, 0), HFD - 1), yc1 = min(max(yi1, 0), HFD - 1);

    const float4* p00 = (const float4*)(g_imgT + (((size_t)b * HFD + yc0) * WFD + xc0) * CDIM);
    const float4* p01 = (const float4*)(g_imgT + (((size_t)b * HFD + yc0) * WFD + xc1) * CDIM);
    const float4* p10 = (const float4*)(g_imgT + (((size_t)b * HFD + yc1) * WFD + xc0) * CDIM);
    const float4* p11 = (const float4*)(g_imgT + (((size_t)b * HFD + yc1) * WFD + xc1) * CDIM);
#pragma unroll 4
    for (int j = 0; j < 32; j++) {
        float4 a = __ldg(p00 + j), bq = __ldg(p01 + j), cq = __ldg(p10 + j), dq = __ldg(p11 + j);
        float r0v = w00 * a.x + w01 * bq.x + w10 * cq.x + w11 * dq.x;
        float r1v = w00 * a.y + w01 * bq.y + w10 * cq.y + w11 * dq.y;
        float r2v = w00 * a.z + w01 * bq.z + w10 * cq.z + w11 * dq.z;
        float r3v = w00 * a.w + w01 * bq.w + w10 * cq.w + w11 * dq.w;
        g_sampT[(size_t)(4 * j + 0) * NPAD + p] = r0v;
        g_sampT[(size_t)(4 * j + 1) * NPAD + p] = r1v;
        g_sampT[(size_t)(4 * j + 2) * NPAD + p] = r2v;
        g_sampT[(size_t)(4 * j + 3) * NPAD + p] = r3v;
    }
}

// ============================================================================
// launch
// ============================================================================
extern "C" void kernel_launch(void* const* d_in, const int* in_sizes, int n_in,
                              void* d_out, int out_size)
{
    const float* x       = (const float*)d_in[0];
    const int*   indices = (const int*)  d_in[1];
    const float* vox     = (const float*)d_in[2];
    const float* pcr     = (const float*)d_in[3];
    const float* trans   = (const float*)d_in[4];
    const float* img     = (const float*)d_in[5];

    int base = 6;
    if (n_in >= 8 && in_sizes[6] == 1 && in_sizes[7] == 1) base = 8;

    const float* fgw1 = (const float*)d_in[base + 0];
    const float* fgb1 = (const float*)d_in[base + 1];
    const float* fgw2 = (const float*)d_in[base + 2];
    const float* fgb2 = (const float*)d_in[base + 3];
    const float* rtw1 = (const float*)d_in[base + 4];
    const float* rtb1 = (const float*)d_in[base + 5];
    const float* rtw2 = (const float*)d_in[base + 6];
    const float* rtb2 = (const float*)d_in[base + 7];
    const float* lew1 = (const float*)d_in[base + 8];
    const float* leb1 = (const float*)d_in[base + 9];
    const float* lew2 = (const float*)d_in[base + 10];
    const float* leb2 = (const float*)d_in[base + 11];
    const float* lng  = (const float*)d_in[base + 12];
    const float* lnb  = (const float*)d_in[base + 13];
    float* out = (float*)d_out;

    const int DSM = 128 * 1024;
    cudaFuncSetAttribute(k_gemmA, cudaFuncAttributeMaxDynamicSharedMemorySize, DSM);
    cudaFuncSetAttribute(k_le1,   cudaFuncAttributeMaxDynamicSharedMemorySize, DSM);
    cudaFuncSetAttribute(k_le2,   cudaFuncAttributeMaxDynamicSharedMemorySize, DSM);

    dim3 tb(32, 32);
    k_tr_img<<<dim3(28, HFD, BDIM), tb>>>(img);
    k_tr_x  <<<dim3(NPTS / 32, 4), tb>>>(x);

    int gblk = NPAD / 128;   // 1563
    k_gemmA<<<gblk, 256, DSM>>>(fgw1, rtw1);

    int pblk = (NPTS + 255) / 256;
    k_point<<<pblk, 256>>>(indices, vox, pcr, trans,
                           fgb1, fgw2, fgb2, rtw1, rtb1, rtw2, rtb2, out);

    k_le1<<<gblk, 256, DSM>>>(lew1, leb1);
    k_le2<<<gblk, 256, DSM>>>(lew2, leb2, lng, lnb, out);
}